// round 16
// baseline (speedup 1.0000x reference)
#include <cuda_runtime.h>
#include <cstdint>
#include <cstddef>

#define B_ 2
#define H_ 16
#define S_ 2048
#define D_ 128
#define SCALE_L2E 0.12751744912f     // (1/sqrt(128)) * log2(e)
#define L2E       1.4426950408889634f

__device__ float    g_inv[B_*H_*S_];           // per-row 1/rowsum (256 KB)
__device__ unsigned g_mbits[B_*S_*(S_/32)];    // bit-packed mask (1 MB, L2-hot)

__device__ __forceinline__ unsigned f2tf(float x){
    unsigned u; asm("cvt.rna.tf32.f32 %0, %1;" : "=r"(u) : "f"(x)); return u;
}
__device__ __forceinline__ void mma_tf32(float* c,
    unsigned a0,unsigned a1,unsigned a2,unsigned a3, unsigned b0, unsigned b1){
    asm volatile("mma.sync.aligned.m16n8k8.row.col.f32.tf32.tf32.f32 "
        "{%0,%1,%2,%3}, {%4,%5,%6,%7}, {%8,%9}, {%0,%1,%2,%3};"
        : "+f"(c[0]),"+f"(c[1]),"+f"(c[2]),"+f"(c[3])
        : "r"(a0),"r"(a1),"r"(a2),"r"(a3),"r"(b0),"r"(b1));
}
__device__ __forceinline__ void cpa16(float* dst, const float* src){
    unsigned d = (unsigned)__cvta_generic_to_shared(dst);
    asm volatile("cp.async.cg.shared.global [%0], [%1], 16;" :: "r"(d), "l"(src));
}
#define CP_COMMIT() asm volatile("cp.async.commit_group;")
#define CP_WAIT0()  asm volatile("cp.async.wait_group 0;")
#define CP_WAIT1()  asm volatile("cp.async.wait_group 1;")

// exp2 on the FMA pipe; clamped at -126; ~4e-5 rel err
__device__ __forceinline__ float exp2_fast(float t){
    t = fmaxf(t, -126.0f);
    float r = t + 12582912.0f;
    float f = t - (r - 12582912.0f);
    float p = 0.009618129f;
    p = fmaf(p, f, 0.055504109f);
    p = fmaf(p, f, 0.240226507f);
    p = fmaf(p, f, 0.693147181f);
    p = fmaf(p, f, 1.0f);
    return __uint_as_float(__float_as_uint(p) + (__float_as_uint(r) << 23));
}

// ===================== Prepass: pack mask into bits =====================
__global__ __launch_bounds__(256)
void maskpack_kernel(const int* __restrict__ mask){
    int idx = blockIdx.x*256 + threadIdx.x;
    int v = mask[idx] != 0;
    unsigned bits = __ballot_sync(~0u, v);
    if ((threadIdx.x&31)==0) g_mbits[idx>>5] = bits;
}

// ===================== Kernel A: e = exp2(masked scores) + row-sum inverses =====================
#define MQ 64
#define KC 64
#define NC (S_/KC)                       // 32
#define PQ 136
#define PK 136
#define QS_FLOATS (MQ*PQ)                // 8704
#define KT_FLOATS (KC*PK)                // 8704
#define A_SMEM_FLOATS (QS_FLOATS + 2*KT_FLOATS + 384)
#define A_SMEM_BYTES  (A_SMEM_FLOATS*4)  // 105984

__device__ __forceinline__ void load_kchunk(float* dst, const float* src, int tid){
    #pragma unroll
    for (int i=0;i<4;i++){
        int c = tid + i*512;
        int row = c>>5, seg = c&31;
        cpa16(dst + row*PK + seg*4, src + (size_t)row*D_ + seg*4);
    }
}

__global__ __launch_bounds__(512,2)
void scores_kernel(const float* __restrict__ q, const float* __restrict__ k,
                   const float* __restrict__ bias, float* __restrict__ attn)
{
    extern __shared__ float smem[];
    float* qs   = smem;
    float* kbuf = smem + QS_FLOATS;
    float* red  = smem + QS_FLOATS + 2*KT_FLOATS;

    const int tid = threadIdx.x, warp = tid>>5, lane = tid&31;
    const int g = lane>>2, ctg = lane&3;
    const int wm = warp&3, wn = warp>>2;
    const int h = blockIdx.y>>1, b = blockIdx.y&1;
    const size_t bh = (size_t)(b*H_+h);
    const int m0 = blockIdx.x*MQ;
    const float* qp = q + (bh*S_+m0)*(size_t)D_;
    const float* kp = k + bh*(size_t)S_*D_;
    float* attn_base = attn + (bh*S_+m0)*(size_t)S_;

    // ---- stage Q as permuted tf32: within 8-group, col c -> (c&3)*2 + (c>>2) ----
    {
        int row = tid>>3, seg = tid&7;
        #pragma unroll
        for (int gi=0; gi<2; ++gi){
            int c0 = seg*16 + gi*8;
            const float* s = qp + (size_t)row*D_ + c0;
            float4 t0 = *(const float4*)(s);
            float4 t1 = *(const float4*)(s+4);
            unsigned* d = (unsigned*)(qs + row*PQ + c0);
            d[0]=f2tf(t0.x); d[2]=f2tf(t0.y); d[4]=f2tf(t0.z); d[6]=f2tf(t0.w);
            d[1]=f2tf(t1.x); d[3]=f2tf(t1.y); d[5]=f2tf(t1.z); d[7]=f2tf(t1.w);
        }
    }
    load_kchunk(kbuf, kp, tid);
    CP_COMMIT();

    float sums[2] = {0.f,0.f};

    #pragma unroll 1
    for (int nc=0; nc<NC; ++nc){
        CP_WAIT0();
        __syncthreads();
        if (nc<NC-1){
            load_kchunk(kbuf + ((nc+1)&1)*KT_FLOATS, kp + (size_t)(nc+1)*KC*D_, tid);
            CP_COMMIT();
        }
        float* kb = kbuf + (nc&1)*KT_FLOATS;

        // ---- in-place convert+permute K chunk to tf32 (1024 8-groups, 2/thread) ----
        #pragma unroll
        for (int i=0;i<2;++i){
            int c = tid + i*512;
            float* p = kb + (c>>4)*PK + (c&15)*8;
            float4 x = *(const float4*)(p);
            float4 y = *(const float4*)(p+4);
            unsigned* u = (unsigned*)p;
            u[0]=f2tf(x.x); u[2]=f2tf(x.y); u[4]=f2tf(x.z); u[6]=f2tf(x.w);
            u[1]=f2tf(y.x); u[3]=f2tf(y.y); u[5]=f2tf(y.z); u[7]=f2tf(y.w);
        }
        __syncthreads();

        float acc[2][4] = {};
        const unsigned* qa = (const unsigned*)(qs + (wm*16+g)*PQ) + 2*ctg;
        const unsigned* kr = (const unsigned*)(kb + (wn*16+g)*PK) + 2*ctg;
        #pragma unroll
        for (int k8=0; k8<16; ++k8){
            uint2 aL = *(const uint2*)(qa + k8*8);
            uint2 aH = *(const uint2*)(qa + 8*PQ + k8*8);
            uint2 b0 = *(const uint2*)(kr + k8*8);
            uint2 b1 = *(const uint2*)(kr + 8*PK + k8*8);
            mma_tf32(acc[0], aL.x,aH.x,aL.y,aH.y, b0.x,b0.y);
            mma_tf32(acc[1], aL.x,aH.x,aL.y,aH.y, b1.x,b1.y);
        }

        // ---- epilogue: bias + bit-mask -> e = exp2 -> attn, row-sums in regs ----
        const int ncol = nc*KC + wn*16 + 2*ctg;
        const int sh = (wn&1)*16 + 2*ctg;
        #pragma unroll
        for (int hi=0; hi<2; ++hi){
            int r = wm*16 + hi*8 + g;
            unsigned wbits = g_mbits[(b*S_ + m0 + r)*(S_/32) + nc*2 + (wn>>1)];
            const float* bp = bias + ((size_t)h*S_ + m0 + r)*S_ + ncol;
            float* ap = attn_base + (size_t)r*S_ + ncol;
            float s = 0.f;
            #pragma unroll
            for (int j=0;j<2;++j){
                float2 bb = *(const float2*)(bp + j*8);
                float c0 = acc[j][hi*2], c1 = acc[j][hi*2+1];
                float x0 = ((wbits>>(sh+j*8  ))&1) ? fmaf(bb.x, L2E, c0*SCALE_L2E) : -126.0f;
                float x1 = ((wbits>>(sh+j*8+1))&1) ? fmaf(bb.y, L2E, c1*SCALE_L2E) : -126.0f;
                float e0 = exp2_fast(x0), e1 = exp2_fast(x1);
                *(float2*)(ap + j*8) = make_float2(e0,e1);
                s += e0+e1;
            }
            sums[hi] += s;
        }
    }

    // ---- row-sum reduce -> g_inv ----
    #pragma unroll
    for (int i=0;i<2;++i){
        sums[i] += __shfl_xor_sync(~0u, sums[i], 1);
        sums[i] += __shfl_xor_sync(~0u, sums[i], 2);
    }
    if (ctg==0){
        red[wn*64 + wm*16 +     g] = sums[0];
        red[wn*64 + wm*16 + 8 + g] = sums[1];
    }
    __syncthreads();
    if (tid < 64){
        float s = red[tid] + red[64+tid] + red[128+tid] + red[192+tid];
        g_inv[bh*S_ + m0 + tid] = 1.0f/s;
    }
}

// ===================== Kernel B: out = (e*inv) @ V, write normalized attn =====================
#define PA 40
#define PB 136
#define SA_FLOATS (128*PA)               // 5120
#define SB_FLOATS (32*PB)                // 4352
#define PV_STAGE  (SA_FLOATS + SB_FLOATS) // 9472
#define PV_SMEM_BYTES ((3*PV_STAGE + 128)*4)   // 114176

__device__ __forceinline__ void load_stageB(float* sa, const float* ap, const float* vp,
                                            int ks, int tid){
    float* sb = sa + SA_FLOATS;
    #pragma unroll
    for (int i=0;i<4;++i){
        int c = tid + i*256;
        int row = c>>3, seg = c&7;
        cpa16(sa + row*PA + seg*4, ap + (size_t)row*S_ + ks*32 + seg*4);
    }
    #pragma unroll
    for (int i=0;i<4;++i){
        int c = tid + i*256;
        int row = c>>5, seg = c&31;
        cpa16(sb + row*PB + seg*4, vp + (size_t)(ks*32+row)*D_ + seg*4);
    }
}

__global__ __launch_bounds__(256,2)
void pv_kernel(float* attn, const float* __restrict__ v, float* __restrict__ out)
{
    extern __shared__ float smemB[];
    float* sinv = smemB + 3*PV_STAGE;
    const int tid = threadIdx.x, wid = tid>>5, lane = tid&31;
    const int g = lane>>2, ctg = lane&3;
    const int wm = wid&3, wn = wid>>2;
    const size_t bh = blockIdx.y;
    const int m0 = blockIdx.x*128;
    float* ap = attn + (bh*S_+m0)*(size_t)S_;
    const float* vp = v + bh*(size_t)S_*D_;

    if (tid < 128) sinv[tid] = __ldg(g_inv + bh*S_ + m0 + tid);

    load_stageB(smemB, ap, vp, 0, tid);
    CP_COMMIT();
    load_stageB(smemB + PV_STAGE, ap, vp, 1, tid);
    CP_COMMIT();

    float acc[2][8][4] = {};
    #pragma unroll 1
    for (int ks=0; ks<64; ++ks){
        if (ks<63) { CP_WAIT1(); } else { CP_WAIT0(); }
        __syncthreads();
        if (ks<62){
            load_stageB(smemB + ((ks+2)%3)*PV_STAGE, ap, vp, ks+2, tid);
            CP_COMMIT();
        }
        float* sa = smemB + (ks%3)*PV_STAGE;
        float* sb = sa + SA_FLOATS;

        // ---- writeback normalized attn (fp32) + convert sa to scaled tf32 (permuted) ----
        #pragma unroll
        for (int i=0;i<2;++i){
            int c = tid + i*256;
            int row = c>>2, grp = c&3;
            float inv = sinv[row];
            float* p = sa + row*PA + grp*8;
            float4 x = *(const float4*)(p);
            float4 y = *(const float4*)(p+4);
            x.x*=inv; x.y*=inv; x.z*=inv; x.w*=inv;
            y.x*=inv; y.y*=inv; y.z*=inv; y.w*=inv;
            float* gdst = ap + (size_t)row*S_ + ks*32 + grp*8;
            *(float4*)(gdst)   = x;
            *(float4*)(gdst+4) = y;
            unsigned* u = (unsigned*)p;
            u[0]=f2tf(x.x); u[2]=f2tf(x.y); u[4]=f2tf(x.z); u[6]=f2tf(x.w);
            u[1]=f2tf(y.x); u[3]=f2tf(y.y); u[5]=f2tf(y.z); u[7]=f2tf(y.w);
        }
        // ---- convert V tile to tf32 in place ----
        #pragma unroll
        for (int i=0;i<4;++i){
            int c = tid + i*256;
            float* p = sb + (c>>5)*PB + (c&31)*4;
            float4 x = *(const float4*)(p);
            unsigned* u = (unsigned*)p;
            u[0]=f2tf(x.x); u[1]=f2tf(x.y); u[2]=f2tf(x.z); u[3]=f2tf(x.w);
        }
        __syncthreads();

        const unsigned* ar = (const unsigned*)(sa + (wm*32+g)*PA) + 2*ctg;
        const unsigned* vb = (const unsigned*)sb + wn*64 + g;
        #pragma unroll
        for (int k8=0; k8<4; ++k8){
            uint2 A0 = *(const uint2*)(ar + k8*8);
            uint2 A1 = *(const uint2*)(ar +  8*PA + k8*8);
            uint2 A2 = *(const uint2*)(ar + 16*PA + k8*8);
            uint2 A3 = *(const uint2*)(ar + 24*PA + k8*8);
            const unsigned* vr  = vb + (k8*8+ctg)*PB;
            const unsigned* vr4 = vr + 4*PB;
            #pragma unroll
            for (int j=0;j<8;++j){
                unsigned b0 = vr[j*8];
                unsigned b1 = vr4[j*8];
                mma_tf32(acc[0][j], A0.x,A1.x,A0.y,A1.y, b0,b1);
                mma_tf32(acc[1][j], A2.x,A3.x,A2.y,A3.y, b0,b1);
            }
        }
    }

    #pragma unroll
    for (int mi=0; mi<2; ++mi){
        float* opL = out + (bh*S_ + m0 + wm*32 + mi*16 + g    )*(size_t)D_ + wn*64 + 2*ctg;
        float* opH = out + (bh*S_ + m0 + wm*32 + mi*16 + g + 8)*(size_t)D_ + wn*64 + 2*ctg;
        #pragma unroll
        for (int j=0;j<8;++j){
            *(float2*)(opL + j*8) = make_float2(acc[mi][j][0], acc[mi][j][1]);
            *(float2*)(opH + j*8) = make_float2(acc[mi][j][2], acc[mi][j][3]);
        }
    }
}

extern "C" void kernel_launch(void* const* d_in, const int* in_sizes, int n_in,
                              void* d_out, int out_size)
{
    const float* q    = (const float*)d_in[0];
    const float* k    = (const float*)d_in[1];
    const float* v    = (const float*)d_in[2];
    const int*   mask = (const int*)  d_in[3];
    const float* bias = (const float*)d_in[4];
    float* out  = (float*)d_out;
    float* attn = out + (size_t)B_*H_*S_*D_;   // tuple output: (out, attn)

    cudaFuncSetAttribute(scores_kernel,
                         cudaFuncAttributeMaxDynamicSharedMemorySize, A_SMEM_BYTES);
    cudaFuncSetAttribute(pv_kernel,
                         cudaFuncAttributeMaxDynamicSharedMemorySize, PV_SMEM_BYTES);

    maskpack_kernel<<<(B_*S_*S_)/256, 256>>>(mask);

    dim3 gA(S_/MQ, 2*H_);
    scores_kernel<<<gA, 512, A_SMEM_BYTES>>>(q, k, bias, attn);

    dim3 gB(S_/128, B_*H_);
    pv_kernel<<<gB, 256, PV_SMEM_BYTES>>>(attn, v, out);
}